// round 13
// baseline (speedup 1.0000x reference)
#include <cuda_runtime.h>
#include <math.h>

// Problem constants: B=2, T=8, N=65536, M=128, F=5, S=128
#define B_ 2
#define T_ 8
#define N_ 65536
#define M_ 128
#define F_ 5
#define S_ 128
#define GAMMA_ 1.1f

#define NTHREADS 256
#define NWARPS 8
#define SUBPTS 4096                 // points per sub-chunk (16/thread)
#define TAILSC 3                    // sub-chunks per tail iteration
#define G_ 4                        // rois per CTA (consecutive m, same slab)
#define NSLOTS (B_ * T_ * M_)       // 2048
#define NGROUPS (NSLOTS / G_)       // 512
#define TOTALPTS (B_ * T_ * N_)     // 1,048,576

// SoA scratch for xy (predicate scan reads these coalesced).
__device__ __align__(16) float g_x[TOTALPTS];
__device__ __align__(16) float g_y[TOTALPTS];

// AoS->SoA transpose: 4 points (= 5 float4) per thread.
__global__ __launch_bounds__(NTHREADS)
void transpose_xy_kernel(const float4* __restrict__ pts4)
{
    const int i4 = blockIdx.x * NTHREADS + threadIdx.x;
    const float4 p0 = pts4[i4 * 5 + 0];
    const float4 p1 = pts4[i4 * 5 + 1];
    const float4 p2 = pts4[i4 * 5 + 2];
    const float4 p3 = pts4[i4 * 5 + 3];
    const float4 p4 = pts4[i4 * 5 + 4];
    ((float4*)g_x)[i4] = make_float4(p0.x, p1.y, p2.z, p3.w);
    ((float4*)g_y)[i4] = make_float4(p0.y, p1.z, p2.w, p4.x);
}

// thr = largest float x with sqrtf(x) <= r  => (d2 <= thr) bit-identical to
// (sqrtf(d2) <= r); removes the per-point sqrt.
__device__ __forceinline__ float roi_setup(const float* __restrict__ roi,
                                           float& cx, float& cy)
{
    cx = roi[0];
    cy = roi[1];
    const float hl = __fmul_rn(roi[3], 0.5f);
    const float hw = __fmul_rn(roi[4], 0.5f);
    const float rr = __fmul_rn(
        sqrtf(__fadd_rn(__fmul_rn(hl, hl), __fmul_rn(hw, hw))), GAMMA_);
    float thr = __fmul_rn(rr, rr);
    while (sqrtf(thr) > rr) thr = __int_as_float(__float_as_int(thr) - 1);
    for (;;) {
        float nxt = __int_as_float(__float_as_int(thr) + 1);
        if (sqrtf(nxt) <= rr) thr = nxt; else break;
    }
    return thr;
}

__device__ __forceinline__ unsigned long long spread4(unsigned v)
{
    return (unsigned long long)(v & 0xFFu)
         | ((unsigned long long)(v & 0xFF00u)     << 8)
         | ((unsigned long long)(v & 0xFF0000u)   << 16)
         | ((unsigned long long)(v & 0xFF000000u) << 24);
}

__device__ __forceinline__ unsigned predicate_mask(
    const float4* xv, const float4* yv, float cx, float cy, float thr)
{
    unsigned msk = 0;
    #pragma unroll
    for (int g = 0; g < 4; g++) {
        const float* xs = (const float*)&xv[g];
        const float* ys = (const float*)&yv[g];
        #pragma unroll
        for (int k = 0; k < 4; k++) {
            const float dx = __fsub_rn(xs[k], cx);
            const float dy = __fsub_rn(ys[k], cy);
            const float d2 = __fadd_rn(__fmul_rn(dx, dx), __fmul_rn(dy, dy));
            msk |= (d2 <= thr ? 1u : 0u) << (g * 4 + k);
        }
    }
    return msk;
}

__device__ __forceinline__ unsigned pack_counts(unsigned msk)
{
    unsigned cp = 0;
    #pragma unroll
    for (int g = 0; g < 4; g++)
        cp |= (unsigned)__popc((msk >> (4 * g)) & 0xFu) << (8 * g);
    return cp;
}

// Byte-packed inclusive warp scan (warp-collective; call convergently).
__device__ __forceinline__ unsigned packed_scan(unsigned cp, int lane, unsigned& excl)
{
    unsigned incl = cp;
    #pragma unroll
    for (int d = 1; d < 32; d <<= 1) {
        const unsigned v = __shfl_up_sync(0xFFFFFFFFu, incl, d);
        if (lane >= d) incl += v;
    }
    excl = incl - cp;
    return __shfl_sync(0xFFFFFFFFu, incl, 31);
}

// Scan-or-zero: convergent fast path when no lane in the warp matched.
__device__ __forceinline__ unsigned scan_or_zero(unsigned msk, int lane, unsigned& excl)
{
    if (__ballot_sync(0xFFFFFFFFu, msk != 0) == 0) { excl = 0; return 0; }
    return packed_scan(pack_counts(msk), lane, excl);
}

// Unpack per-warp counts for one roi, write this thread's matches in order.
__device__ __forceinline__ int write_subchunk(
    const unsigned long long* __restrict__ slotcnt, int wid, int tid,
    unsigned mask, unsigned excl, int total, int ptbase,
    const float* __restrict__ P, float* __restrict__ O)
{
    unsigned long long tot64 = 0, bef64 = 0;
    #pragma unroll
    for (int w = 0; w < NWARPS; w++) {
        const unsigned long long v = slotcnt[w];
        tot64 += v;
        if (w < wid) bef64 += v;
    }
    const unsigned a = (unsigned)tot64 + (unsigned)(tot64 >> 32);
    const int chunkTotal = (int)((a & 0xFFFFu) + (a >> 16));

    if (mask) {
        int fieldPrefix = 0;
        #pragma unroll
        for (int f4 = 0; f4 < 4; f4++) {
            const int tj = (int)((tot64 >> (16 * f4)) & 0xFFFFu);
            const int bj = (int)((bef64 >> (16 * f4)) & 0xFFFFu);
            int r = total + fieldPrefix + bj + (int)((excl >> (8 * f4)) & 0xFFu);
            unsigned mj = (mask >> (4 * f4)) & 0xFu;
            while (mj) {
                const int k = __ffs(mj) - 1;
                mj &= mj - 1;
                if (r < S_) {
                    const int pt = ptbase + f4 * (NTHREADS * 4) + tid * 4 + k;
                    const float* src = P + (size_t)pt * F_;
                    float* dst = O + r * F_;
                    #pragma unroll
                    for (int f = 0; f < F_; f++) dst[f] = src[f];
                }
                r++;
            }
            fieldPrefix += tj;
        }
    }
    return chunkTotal;
}

// One CTA per group of G_=4 consecutive slots (same b,t => same slab).
// Chunk data is loaded into registers ONCE and tested against all 4 rois.
// Fallback slots (t!=0, vl==0) are skipped here; a later kernel copies the
// frame-0 result into them.
__global__ __launch_bounds__(NTHREADS)
void voxel_pool_kernel(const float* __restrict__ pts,
                       const float* __restrict__ rois,
                       const int* __restrict__ vl,
                       float* __restrict__ out)
{
    const int slot0 = blockIdx.x * G_;
    const int m0 = slot0 & (M_ - 1);
    const int t = (slot0 >> 7) & (T_ - 1);
    const int b = slot0 >> 10;
    const int tid  = threadIdx.x;
    const int lane = tid & 31;
    const int wid  = tid >> 5;

    // Active = native slots only (use_t == t).
    unsigned act = 0;
    #pragma unroll
    for (int j = 0; j < G_; j++) {
        if (t == 0 || vl[slot0 + j] != 0) act |= 1u << j;
    }
    if (act == 0) return;

    const int slab = b * T_ + t;
    const float*  P  = pts + (size_t)slab * N_ * F_;
    const float4* X4 = (const float4*)(g_x + (size_t)slab * N_);
    const float4* Y4 = (const float4*)(g_y + (size_t)slab * N_);

    __shared__ unsigned long long s_cnt[2][TAILSC][G_][NWARPS];

    // Chunk-0 loads issued first (independent of roi params).
    float4 xv0[4], yv0[4];
    #pragma unroll
    for (int g = 0; g < 4; g++) {
        xv0[g] = X4[g * NTHREADS + tid];
        yv0[g] = Y4[g * NTHREADS + tid];
    }

    float cx[G_], cy[G_], thr[G_];
    float* O[G_];
    #pragma unroll
    for (int j = 0; j < G_; j++) {
        if (act & (1u << j)) {
            thr[j] = roi_setup(rois + ((size_t)slab * M_ + m0 + j) * 7,
                               cx[j], cy[j]);
        } else {
            cx[j] = 0.0f; cy[j] = 0.0f; thr[j] = -1.0f;   // never matches
        }
        O[j] = out + ((size_t)(b * M_ + m0 + j) * (T_ * S_) + (size_t)t * S_) * F_;
    }

    int totals[G_] = {0, 0, 0, 0};

    // ---- Chunk 0 (4096 points, shared across the 4 rois) ----
    {
        unsigned mask0[G_], excl0[G_];
        #pragma unroll
        for (int j = 0; j < G_; j++) {
            mask0[j] = predicate_mask(xv0, yv0, cx[j], cy[j], thr[j]);
            const unsigned wt = scan_or_zero(mask0[j], lane, excl0[j]);
            if (lane == 0) s_cnt[0][0][j][wid] = spread4(wt);
        }
        __syncthreads();
        #pragma unroll
        for (int j = 0; j < G_; j++) {
            if (act & (1u << j)) {
                totals[j] = write_subchunk(s_cnt[0][0][j], wid, tid,
                                           mask0[j], excl0[j], 0, 0, P, O[j]);
            }
        }
    }

    // ---- Tail: 5 iterations x 3 sub-chunks, one barrier each ----
    for (int it = 0; it < 5; it++) {
        bool alldone = true;
        #pragma unroll
        for (int j = 0; j < G_; j++) {
            if ((act & (1u << j)) && totals[j] < S_) alldone = false;
        }
        if (alldone) break;   // uniform

        const int buf = (it & 1) ^ 1;
        const int ptbase = SUBPTS + it * (TAILSC * SUBPTS);

        unsigned masks[TAILSC][G_], excls[TAILSC][G_];
        #pragma unroll
        for (int sc = 0; sc < TAILSC; sc++) {
            const int off4 = (ptbase + sc * SUBPTS) / 4;
            float4 xv[4], yv[4];
            #pragma unroll
            for (int g = 0; g < 4; g++) {
                xv[g] = X4[off4 + g * NTHREADS + tid];
                yv[g] = Y4[off4 + g * NTHREADS + tid];
            }
            #pragma unroll
            for (int j = 0; j < G_; j++) {
                masks[sc][j] = predicate_mask(xv, yv, cx[j], cy[j], thr[j]);
                const unsigned wt = scan_or_zero(masks[sc][j], lane, excls[sc][j]);
                if (lane == 0) s_cnt[buf][sc][j][wid] = spread4(wt);
            }
        }
        __syncthreads();

        #pragma unroll
        for (int sc = 0; sc < TAILSC; sc++) {
            #pragma unroll
            for (int j = 0; j < G_; j++) {
                if ((act & (1u << j)) && totals[j] < S_) {
                    totals[j] += write_subchunk(s_cnt[buf][sc][j], wid, tid,
                                                masks[sc][j], excls[sc][j],
                                                totals[j],
                                                ptbase + sc * SUBPTS, P, O[j]);
                }
            }
        }
    }

    // Zero-fill rows [written, S) for active rois.
    #pragma unroll
    for (int j = 0; j < G_; j++) {
        if (act & (1u << j)) {
            const int written = (totals[j] < S_) ? totals[j] : S_;
            const int zfl = (S_ - written) * F_;
            for (int i = tid; i < zfl; i += NTHREADS) {
                O[j][written * F_ + i] = 0.0f;
            }
        }
    }
}

// Fallback slots copy the frame-0 pool result of the same (b, m).
// Runs after voxel_pool_kernel; source (t=0 rows) is always computed there.
__global__ __launch_bounds__(128)
void copy_fallback_kernel(const int* __restrict__ vl, float* __restrict__ out)
{
    const int slot = blockIdx.x;            // (b*T + t)*M + m
    const int m = slot & (M_ - 1);
    const int t = (slot >> 7) & (T_ - 1);
    const int b = slot >> 10;
    if (t == 0 || vl[slot] != 0) return;

    float4* dst = (float4*)(out + ((size_t)(b * M_ + m) * (T_ * S_)
                                   + (size_t)t * S_) * F_);
    const float4* src = (const float4*)(out + (size_t)(b * M_ + m)
                                              * (T_ * S_) * F_);
    // S*F = 640 floats = 160 float4; both bases are 16B-aligned.
    for (int i = threadIdx.x; i < (S_ * F_) / 4; i += 128) {
        dst[i] = src[i];
    }
}

extern "C" void kernel_launch(void* const* d_in, const int* in_sizes, int n_in,
                              void* d_out, int out_size)
{
    const float* pts  = (const float*)d_in[0];  // [B,T,N,F] f32
    const float* rois = (const float*)d_in[1];  // [B,T,M,7] f32
    const int*   vl   = (const int*)d_in[2];    // [B,T,M]   i32
    float* out = (float*)d_out;                 // [B,M,T*S,F] f32

    (void)in_sizes; (void)n_in; (void)out_size;
    transpose_xy_kernel<<<TOTALPTS / 4 / NTHREADS, NTHREADS>>>((const float4*)pts);
    voxel_pool_kernel<<<NGROUPS, NTHREADS>>>(pts, rois, vl, out);
    copy_fallback_kernel<<<NSLOTS, 128>>>(vl, out);
}

// round 14
// speedup vs baseline: 1.8052x; 1.8052x over previous
#include <cuda_runtime.h>
#include <math.h>

// Problem constants: B=2, T=8, N=65536, M=128, F=5, S=128
#define B_ 2
#define T_ 8
#define N_ 65536
#define M_ 128
#define F_ 5
#define S_ 128
#define GAMMA_ 1.1f

#define NTHREADS 256
#define NWARPS 8
#define SUBPTS 4096                 // points per sub-chunk (16/thread)
#define TAILSC 3                    // sub-chunks per tail iteration
#define NSLOTS (B_ * T_ * M_)       // 2048 output slots
#define TOTALPTS (B_ * T_ * N_)     // 1,048,576

// SoA scratch for xy + per-slot precomputed params + execution order.
__device__ __align__(16) float g_x[TOTALPTS];
__device__ __align__(16) float g_y[TOTALPTS];
__device__ float g_cx[NSLOTS];
__device__ float g_cy[NSLOTS];
__device__ float g_thr[NSLOTS];
__device__ int   g_slab[NSLOTS];
__device__ int   g_order[NSLOTS];
__device__ int   g_nfront, g_nback;

// AoS->SoA transpose: 4 points (= 5 float4) per thread. Thread 0 of block 0
// resets the ordering counters (stream-ordered before classify).
__global__ __launch_bounds__(NTHREADS)
void transpose_xy_kernel(const float4* __restrict__ pts4)
{
    if (blockIdx.x == 0 && threadIdx.x == 0) { g_nfront = 0; g_nback = 0; }
    const int i4 = blockIdx.x * NTHREADS + threadIdx.x;
    const float4 p0 = pts4[i4 * 5 + 0];
    const float4 p1 = pts4[i4 * 5 + 1];
    const float4 p2 = pts4[i4 * 5 + 2];
    const float4 p3 = pts4[i4 * 5 + 3];
    const float4 p4 = pts4[i4 * 5 + 4];
    ((float4*)g_x)[i4] = make_float4(p0.x, p1.y, p2.z, p3.w);
    ((float4*)g_y)[i4] = make_float4(p0.y, p1.z, p2.w, p4.x);
}

// thr = largest float x with sqrtf(x) <= r  => (d2 <= thr) bit-identical to
// (sqrtf(d2) <= r); removes the per-point sqrt.
__device__ __forceinline__ float roi_setup(const float* __restrict__ roi,
                                           float& cx, float& cy)
{
    cx = roi[0];
    cy = roi[1];
    const float hl = __fmul_rn(roi[3], 0.5f);
    const float hw = __fmul_rn(roi[4], 0.5f);
    const float rr = __fmul_rn(
        sqrtf(__fadd_rn(__fmul_rn(hl, hl), __fmul_rn(hw, hw))), GAMMA_);
    float thr = __fmul_rn(rr, rr);
    while (sqrtf(thr) > rr) thr = __int_as_float(__float_as_int(thr) - 1);
    for (;;) {
        float nxt = __int_as_float(__float_as_int(thr) + 1);
        if (sqrtf(nxt) <= rr) thr = nxt; else break;
    }
    return thr;
}

// Per-slot params + straggler-first ordering. Expected matches per scanned
// point ~ thr * exp(-|c|^2/2) / 2. A roi finishing at chunk 0 needs score
// >~ 0.0625; anything below 0.05 likely scans multiple chunks -> FRONT of
// the execution queue so its deep scan overlaps the bulk. Ordering only
// affects scheduling; outputs are per-slot disjoint => deterministic result.
__global__ __launch_bounds__(NTHREADS)
void classify_kernel(const float* __restrict__ rois, const int* __restrict__ vl)
{
    const int slot = blockIdx.x * NTHREADS + threadIdx.x;   // (b*T + t)*M + m
    const int m = slot & (M_ - 1);
    const int t = (slot >> 7) & (T_ - 1);
    const int b = slot >> 10;

    int use_t = t;
    if (t != 0 && vl[slot] == 0) use_t = 0;
    const int slab = b * T_ + use_t;

    float cx, cy;
    const float thr = roi_setup(rois + ((size_t)slab * M_ + m) * 7, cx, cy);
    g_cx[slot] = cx;
    g_cy[slot] = cy;
    g_thr[slot] = thr;
    g_slab[slot] = slab;

    const float score = thr * __expf(-0.5f * (cx * cx + cy * cy));
    if (score < 0.05f) {
        const int p = atomicAdd(&g_nfront, 1);
        g_order[p] = slot;
    } else {
        const int p = atomicAdd(&g_nback, 1);
        g_order[NSLOTS - 1 - p] = slot;
    }
}

__device__ __forceinline__ unsigned long long spread4(unsigned v)
{
    return (unsigned long long)(v & 0xFFu)
         | ((unsigned long long)(v & 0xFF00u)     << 8)
         | ((unsigned long long)(v & 0xFF0000u)   << 16)
         | ((unsigned long long)(v & 0xFF000000u) << 24);
}

__device__ __forceinline__ unsigned predicate_mask(
    const float4* xv, const float4* yv, float cx, float cy, float thr)
{
    unsigned msk = 0;
    #pragma unroll
    for (int j = 0; j < 4; j++) {
        const float* xs = (const float*)&xv[j];
        const float* ys = (const float*)&yv[j];
        #pragma unroll
        for (int k = 0; k < 4; k++) {
            const float dx = __fsub_rn(xs[k], cx);
            const float dy = __fsub_rn(ys[k], cy);
            const float d2 = __fadd_rn(__fmul_rn(dx, dx), __fmul_rn(dy, dy));
            msk |= (d2 <= thr ? 1u : 0u) << (j * 4 + k);
        }
    }
    return msk;
}

__device__ __forceinline__ unsigned pack_counts(unsigned msk)
{
    unsigned cp = 0;
    #pragma unroll
    for (int j = 0; j < 4; j++)
        cp |= (unsigned)__popc((msk >> (4 * j)) & 0xFu) << (8 * j);
    return cp;
}

// Byte-packed inclusive warp scan; returns warp total, sets excl. Must be
// called CONVERGENTLY by all 32 lanes (warp-collective shfls inside).
__device__ __forceinline__ unsigned packed_scan(unsigned cp, int lane, unsigned& excl)
{
    unsigned incl = cp;
    #pragma unroll
    for (int d = 1; d < 32; d <<= 1) {
        const unsigned v = __shfl_up_sync(0xFFFFFFFFu, incl, d);
        if (lane >= d) incl += v;
    }
    excl = incl - cp;
    return __shfl_sync(0xFFFFFFFFu, incl, 31);
}

// Unpack per-warp counts; RECORD this thread's matched point indices into
// the smem rank->index table (no global traffic here). Returns chunk total.
__device__ __forceinline__ int record_subchunk(
    const unsigned long long* __restrict__ slotcnt, int wid, int tid,
    unsigned mask, unsigned excl, int total, int ptbase,
    int* __restrict__ s_idx)
{
    unsigned long long tot64 = 0, bef64 = 0;
    #pragma unroll
    for (int w = 0; w < NWARPS; w++) {
        const unsigned long long v = slotcnt[w];
        tot64 += v;
        if (w < wid) bef64 += v;
    }
    const unsigned a = (unsigned)tot64 + (unsigned)(tot64 >> 32);
    const int chunkTotal = (int)((a & 0xFFFFu) + (a >> 16));

    if (mask) {
        int fieldPrefix = 0;
        #pragma unroll
        for (int j = 0; j < 4; j++) {
            const int tj = (int)((tot64 >> (16 * j)) & 0xFFFFu);
            const int bj = (int)((bef64 >> (16 * j)) & 0xFFFFu);
            int r = total + fieldPrefix + bj + (int)((excl >> (8 * j)) & 0xFFu);
            unsigned mj = (mask >> (4 * j)) & 0xFu;
            while (mj) {
                const int k = __ffs(mj) - 1;
                mj &= mj - 1;
                if (r < S_) {
                    s_idx[r] = ptbase + j * (NTHREADS * 4) + tid * 4 + k;
                }
                r++;
            }
            fieldPrefix += tj;
        }
    }
    return chunkTotal;
}

// One CTA per output slot, executed in straggler-first order. The scan loop
// only records matched indices in smem; ONE coalesced pass at the end
// gathers the 5 fields per match and writes (or zero-fills) all 640 output
// floats of this slot.
__global__ __launch_bounds__(NTHREADS)
void voxel_pool_kernel(const float* __restrict__ pts, float* __restrict__ out)
{
    const int slot = g_order[blockIdx.x];
    const int m = slot & (M_ - 1);
    const int t = (slot >> 7) & (T_ - 1);
    const int b = slot >> 10;
    const int tid  = threadIdx.x;
    const int lane = tid & 31;
    const int wid  = tid >> 5;

    const int slab = g_slab[slot];
    const float*  P  = pts + (size_t)slab * N_ * F_;
    const float4* X4 = (const float4*)(g_x + (size_t)slab * N_);
    const float4* Y4 = (const float4*)(g_y + (size_t)slab * N_);
    float* O = out + ((size_t)(b * M_ + m) * (T_ * S_) + (size_t)t * S_) * F_;

    __shared__ unsigned long long s_cnt[2][TAILSC][NWARPS];
    __shared__ int s_idx[S_];

    // Chunk-0 loads issued immediately.
    float4 xv0[4], yv0[4];
    #pragma unroll
    for (int j = 0; j < 4; j++) {
        xv0[j] = X4[j * NTHREADS + tid];
        yv0[j] = Y4[j * NTHREADS + tid];
    }

    const float cx  = g_cx[slot];
    const float cy  = g_cy[slot];
    const float thr = g_thr[slot];

    // ---- Chunk 0 (4096 points) ----  (all collectives convergent)
    const unsigned mask0 = predicate_mask(xv0, yv0, cx, cy, thr);
    unsigned excl0;
    const unsigned wt0 = packed_scan(pack_counts(mask0), lane, excl0);
    if (lane == 0) s_cnt[0][0][wid] = spread4(wt0);
    __syncthreads();

    int total = record_subchunk(s_cnt[0][0], wid, tid, mask0, excl0, 0, 0, s_idx);

    // ---- Tail: 5 iterations x 3 sub-chunks (12288 pts, one barrier each) ----
    for (int it = 0; it < 5 && total < S_; it++) {
        const int buf = (it & 1) ^ 1;
        const int ptbase = SUBPTS + it * (TAILSC * SUBPTS);

        unsigned masks[TAILSC], excls[TAILSC];
        #pragma unroll
        for (int sc = 0; sc < TAILSC; sc++) {
            const int off4 = (ptbase + sc * SUBPTS) / 4;
            float4 xv[4], yv[4];
            #pragma unroll
            for (int j = 0; j < 4; j++) {
                xv[j] = X4[off4 + j * NTHREADS + tid];
                yv[j] = Y4[off4 + j * NTHREADS + tid];
            }
            masks[sc] = predicate_mask(xv, yv, cx, cy, thr);
            const unsigned wt = packed_scan(pack_counts(masks[sc]), lane, excls[sc]);
            if (lane == 0) s_cnt[buf][sc][wid] = spread4(wt);
        }
        __syncthreads();

        #pragma unroll
        for (int sc = 0; sc < TAILSC; sc++) {
            if (total < S_) {
                total += record_subchunk(s_cnt[buf][sc], wid, tid,
                                         masks[sc], excls[sc], total,
                                         ptbase + sc * SUBPTS, s_idx);
            }
        }
    }

    // ---- Final coalesced emit: gather + write all S*F = 640 floats ----
    __syncthreads();   // s_idx written by all threads above
    const int written = (total < S_) ? total : S_;
    #pragma unroll
    for (int base = 0; base < S_ * F_; base += NTHREADS) {
        const int f = base + tid;              // 640 = 2*NTHREADS + 128
        if (f < S_ * F_) {
            const int row = f / F_;
            const int fld = f - row * F_;
            O[f] = (row < written)
                 ? P[(size_t)s_idx[row] * F_ + fld]
                 : 0.0f;
        }
    }
}

extern "C" void kernel_launch(void* const* d_in, const int* in_sizes, int n_in,
                              void* d_out, int out_size)
{
    const float* pts  = (const float*)d_in[0];  // [B,T,N,F] f32
    const float* rois = (const float*)d_in[1];  // [B,T,M,7] f32
    const int*   vl   = (const int*)d_in[2];    // [B,T,M]   i32
    float* out = (float*)d_out;                 // [B,M,T*S,F] f32

    (void)in_sizes; (void)n_in; (void)out_size;
    transpose_xy_kernel<<<TOTALPTS / 4 / NTHREADS, NTHREADS>>>((const float4*)pts);
    classify_kernel<<<NSLOTS / NTHREADS, NTHREADS>>>(rois, vl);
    voxel_pool_kernel<<<NSLOTS, NTHREADS>>>(pts, out);
}